// round 1
// baseline (speedup 1.0000x reference)
#include <cuda_runtime.h>

#define NPTS      2000000
#define NLEV      12
#define HSIZE     524288
#define HMASK     (HSIZE - 1)

#define D_IN   24
#define D_H1   32
#define D_H2   16
#define D_H3   8

// smem float offsets (all multiples of 4 for float4 access)
#define OFF_W1  0           // 32*24 = 768
#define OFF_B1  768         // 32
#define OFF_W2  800         // 16*32 = 512
#define OFF_B2  1312        // 16
#define OFF_W3  1328        // 8*16 = 128
#define OFF_B3  1456        // 8
#define OFF_W4  1464        // 8
#define OFF_B4  1472        // 1
#define SMEM_FLOATS 1476

__device__ __forceinline__ float lrelu(float v) {
    return v > 0.0f ? v : 0.01f * v;
}

__global__ __launch_bounds__(256)
void nhgrid_kernel(const float2* __restrict__ x,
                   const float*  __restrict__ tables,
                   const float*  __restrict__ W1, const float* __restrict__ b1,
                   const float*  __restrict__ W2, const float* __restrict__ b2,
                   const float*  __restrict__ W3, const float* __restrict__ b3,
                   const float*  __restrict__ W4, const float* __restrict__ b4,
                   float* __restrict__ out, int n_points)
{
    __shared__ float sm[SMEM_FLOATS];

    // cooperative weight staging
    int tid = threadIdx.x;
    for (int i = tid; i < 768; i += 256) sm[OFF_W1 + i] = W1[i];
    for (int i = tid; i < 32;  i += 256) sm[OFF_B1 + i] = b1[i];
    for (int i = tid; i < 512; i += 256) sm[OFF_W2 + i] = W2[i];
    for (int i = tid; i < 16;  i += 256) sm[OFF_B2 + i] = b2[i];
    for (int i = tid; i < 128; i += 256) sm[OFF_W3 + i] = W3[i];
    for (int i = tid; i < 8;   i += 256) sm[OFF_B3 + i] = b3[i];
    for (int i = tid; i < 8;   i += 256) sm[OFF_W4 + i] = W4[i];
    if (tid == 0) sm[OFF_B4] = b4[0];
    __syncthreads();

    int n = blockIdx.x * blockDim.x + threadIdx.x;
    if (n >= n_points) return;

    // spacings = 256.0 // 1.6**(11-i) with Python-double floor-division semantics:
    // 1.6 (binary64) > 1.6 exactly, so 256//1.6 = 159 and 256//1.6^2 = 99.
    const float spacings[NLEV] = {1.f, 2.f, 3.f, 5.f, 9.f, 15.f, 24.f, 39.f,
                                  62.f, 99.f, 159.f, 256.f};

    float2 p = x[n];
    float x0 = p.x * 0.5f + 0.5f;
    float x1 = p.y * 0.5f + 0.5f;

    float f[D_IN];
    #pragma unroll
    for (int i = 0; i < NLEV; i++) {
        float s = spacings[i];
        int d0 = (int)floorf(x0 * s);
        int d1 = (int)floorf(x1 * s);
        // int64 hash mod 2^19 == uint32-wrapping arithmetic masked to 19 bits
        unsigned h = ((unsigned)d0 * 73856093u + (unsigned)d1 * 19349663u) & HMASK;
        const float2 t = *reinterpret_cast<const float2*>(
            tables + ((size_t)i * HSIZE + h) * 2);
        f[2 * i]     = t.x;
        f[2 * i + 1] = t.y;
    }

    const float4* sW1 = reinterpret_cast<const float4*>(sm + OFF_W1);
    const float4* sW2 = reinterpret_cast<const float4*>(sm + OFF_W2);
    const float4* sW3 = reinterpret_cast<const float4*>(sm + OFF_W3);
    const float4* sW4 = reinterpret_cast<const float4*>(sm + OFF_W4);

    // layer 1: 24 -> 32
    float h1[D_H1];
    #pragma unroll
    for (int i = 0; i < D_H1; i++) {
        float a = sm[OFF_B1 + i];
        #pragma unroll
        for (int j = 0; j < D_IN / 4; j++) {
            float4 w = sW1[i * (D_IN / 4) + j];
            a += w.x * f[4*j] + w.y * f[4*j+1] + w.z * f[4*j+2] + w.w * f[4*j+3];
        }
        h1[i] = lrelu(a);
    }

    // layer 2: 32 -> 16
    float h2[D_H2];
    #pragma unroll
    for (int i = 0; i < D_H2; i++) {
        float a = sm[OFF_B2 + i];
        #pragma unroll
        for (int j = 0; j < D_H1 / 4; j++) {
            float4 w = sW2[i * (D_H1 / 4) + j];
            a += w.x * h1[4*j] + w.y * h1[4*j+1] + w.z * h1[4*j+2] + w.w * h1[4*j+3];
        }
        h2[i] = lrelu(a);
    }

    // layer 3: 16 -> 8
    float h3[D_H3];
    #pragma unroll
    for (int i = 0; i < D_H3; i++) {
        float a = sm[OFF_B3 + i];
        #pragma unroll
        for (int j = 0; j < D_H2 / 4; j++) {
            float4 w = sW3[i * (D_H2 / 4) + j];
            a += w.x * h2[4*j] + w.y * h2[4*j+1] + w.z * h2[4*j+2] + w.w * h2[4*j+3];
        }
        h3[i] = lrelu(a);
    }

    // layer 4: 8 -> 1, then lrelu applied twice (forward + trueRange=False extra)
    float z = sm[OFF_B4];
    #pragma unroll
    for (int j = 0; j < D_H3 / 4; j++) {
        float4 w = sW4[j];
        z += w.x * h3[4*j] + w.y * h3[4*j+1] + w.z * h3[4*j+2] + w.w * h3[4*j+3];
    }
    z = lrelu(z);
    z = lrelu(z);

    out[n] = z;
}

extern "C" void kernel_launch(void* const* d_in, const int* in_sizes, int n_in,
                              void* d_out, int out_size)
{
    const float2* x      = (const float2*)d_in[0];
    const float*  tables = (const float*) d_in[1];
    const float*  W1     = (const float*) d_in[2];
    const float*  b1     = (const float*) d_in[3];
    const float*  W2     = (const float*) d_in[4];
    const float*  b2     = (const float*) d_in[5];
    const float*  W3     = (const float*) d_in[6];
    const float*  b3     = (const float*) d_in[7];
    const float*  W4     = (const float*) d_in[8];
    const float*  b4     = (const float*) d_in[9];
    float* out = (float*)d_out;

    int n_points = in_sizes[0] / 2;  // x is [N,2]
    int threads = 256;
    int blocks = (n_points + threads - 1) / threads;
    nhgrid_kernel<<<blocks, threads>>>(x, tables, W1, b1, W2, b2, W3, b3, W4, b4,
                                       out, n_points);
}